// round 8
// baseline (speedup 1.0000x reference)
#include <cuda_runtime.h>

#define B_ 16
#define N_ 1024
#define D_ 64
#define C_ 64
#define K_ 20
#define EPS_ 0.001f
#define PAIRS_ 4          // node-pairs per group; block = 2 groups * 4 pairs * 2 nodes = 16 nodes

// scratch (no cudaMalloc allowed)
__device__ int   g_nn_idx[B_ * N_ * K_];
__device__ float g_f0[B_ * N_];

// ---------------------------------------------------------------------------
// packed fp32x2 helpers (sm_103a FFMA2)
// ---------------------------------------------------------------------------
__device__ __forceinline__ unsigned long long pack2(float x, float y) {
    float2 f = make_float2(x, y);
    return *reinterpret_cast<unsigned long long*>(&f);
}
__device__ __forceinline__ float2 unpack2(unsigned long long u) {
    return *reinterpret_cast<float2*>(&u);
}
__device__ __forceinline__ unsigned long long ffma2(unsigned long long a,
                                                    unsigned long long b,
                                                    unsigned long long c) {
    unsigned long long d;
    asm("fma.rn.f32x2 %0, %1, %2, %3;" : "=l"(d) : "l"(a), "l"(b), "l"(c));
    return d;
}

// ---------------------------------------------------------------------------
// Kernel 0: densify f0 = feats[:,:,0]
// ---------------------------------------------------------------------------
__global__ void extract_f0_kernel(const float* __restrict__ feats) {
    int i = blockIdx.x * blockDim.x + threadIdx.x;
    if (i < B_ * N_) g_f0[i] = feats[(size_t)i * D_];
}

// ---------------------------------------------------------------------------
// Kernel 1: exact top-20 smallest of a[j] = adj[b,n,j]*|f0[b,j]-f0[b,n]|.
// Keys unique (index embedded); REDUX-based argmin; lowest-index tie-break
// matches jax.lax.top_k.
// ---------------------------------------------------------------------------
__global__ void topk_kernel(const float* __restrict__ adj) {
    const int row  = blockIdx.x;            // b*N + n
    const int b    = row >> 10;
    const int tid  = threadIdx.x;           // 256 threads
    const int lane = tid & 31;
    const int wid  = tid >> 5;              // 8 warps

    const float  f0n  = g_f0[row];
    const float* arow = adj + (size_t)row * N_;
    const float* f0b  = g_f0 + b * N_;

    unsigned long long key[4];
#pragma unroll
    for (int t = 0; t < 4; t++) {
        int j = tid + t * 256;
        float a = arow[j] * fabsf(f0b[j] - f0n);
        key[t] = ((unsigned long long)__float_as_uint(a) << 32) | (unsigned)j;
    }
#define CSWP(x, y) { unsigned long long lo = (x) < (y) ? (x) : (y); \
                     unsigned long long hi = (x) < (y) ? (y) : (x); (x) = lo; (y) = hi; }
    CSWP(key[0], key[1]); CSWP(key[2], key[3]);
    CSWP(key[0], key[2]); CSWP(key[1], key[3]);
    CSWP(key[1], key[2]);
#undef CSWP

    __shared__ unsigned long long cand[8][K_];

#pragma unroll 1
    for (int i = 0; i < K_; i++) {
        unsigned v = (unsigned)(key[0] >> 32);
        unsigned m = __reduce_min_sync(0xffffffffu, v);
        unsigned ic = (v == m) ? (unsigned)key[0] : 0xffffffffu;
        unsigned mi = __reduce_min_sync(0xffffffffu, ic);
        if (lane == 0) cand[wid][i] = ((unsigned long long)m << 32) | mi;
        if (v == m && (unsigned)key[0] == mi) {
            key[0] = key[1]; key[1] = key[2]; key[2] = key[3];
            key[3] = ~0ULL;
        }
    }
    __syncthreads();

    if (wid == 0) {
        int q = 0;
        const int out_base = row * K_;
#pragma unroll 1
        for (int i = 0; i < K_; i++) {
            unsigned long long myk = (lane < 8) ? cand[lane][q] : ~0ULL;
            unsigned v = (unsigned)(myk >> 32);
            unsigned m = __reduce_min_sync(0xffffffffu, v);
            unsigned ic = (v == m) ? (unsigned)myk : 0xffffffffu;
            unsigned mi = __reduce_min_sync(0xffffffffu, ic);
            if (lane == 0) g_nn_idx[out_base + i] = (int)mi;
            if (v == m && (unsigned)myk == mi) q++;
        }
    }
}

// ---------------------------------------------------------------------------
// Kernel 2: fused gather + MLP + mean (R5 structure, best so far).
// ---------------------------------------------------------------------------
#define SM_W1C  0
#define SM_CF   4096
#define SM_DBUF (4096 + 256)
#define SM_HBUF (4096 + 256 + 5120)
#define SM_FLOATS (4096 + 256 + 5120 + 5120)

__global__ void __launch_bounds__(128, 2) edgeconv_kernel(
    const float* __restrict__ feats,
    const float* __restrict__ w1,  const float* __restrict__ b1,
    const float* __restrict__ g1,  const float* __restrict__ be1,
    const float* __restrict__ mu1, const float* __restrict__ v1,
    const float* __restrict__ w2,  const float* __restrict__ b2,
    const float* __restrict__ g2,  const float* __restrict__ be2,
    const float* __restrict__ mu2, const float* __restrict__ v2,
    float* __restrict__ out)
{
    extern __shared__ __align__(16) float sm[];
    float* w1c_s = sm + SM_W1C;

    const int tid = threadIdx.x;
    const int c   = tid & (C_ - 1);
    const int grp = tid >> 6;
    const int bbase = ((blockIdx.x * 16) >> 10) << 10;   // b*N (const per block)

    float* cfA = sm + SM_CF + (grp * 2 + 0) * C_;
    float* cfB = sm + SM_CF + (grp * 2 + 1) * C_;
    float* dA  = sm + SM_DBUF + (grp * 2 + 0) * (K_ * C_);
    float* dB  = sm + SM_DBUF + (grp * 2 + 1) * (K_ * C_);
    float* hA  = sm + SM_HBUF + (grp * 2 + 0) * (K_ * C_);
    float* hB  = sm + SM_HBUF + (grp * 2 + 1) * (K_ * C_);

    const float s1c = g1[c] * rsqrtf(v1[c] + EPS_);
    const float b1f = (b1[c] - mu1[c]) * s1c + be1[c];
    const float s2c = g2[c] * rsqrtf(v2[c] + EPS_);
    const float b2f = (b2[c] - mu2[c]) * s2c + be2[c];

    unsigned long long W1[D_ / 2];   // packed folded w1[64+2i..+1][c]
    unsigned long long W2[C_ / 2];   // packed folded w2[2i..+1][c]
#pragma unroll
    for (int i = 0; i < D_ / 2; i++)
        W1[i] = pack2(w1[(D_ + 2 * i) * C_ + c] * s1c,
                      w1[(D_ + 2 * i + 1) * C_ + c] * s1c);
#pragma unroll
    for (int i = 0; i < C_ / 2; i++)
        W2[i] = pack2(w2[(2 * i) * C_ + c] * s2c,
                      w2[(2 * i + 1) * C_ + c] * s2c);
    if (grp == 0) {
#pragma unroll
        for (int d = 0; d < D_; d++) w1c_s[d * C_ + c] = w1[d * C_ + c] * s1c;
    }

    // gather pair 0 directly
    {
        const int nA = blockIdx.x * 16 + grp * 2;
        const int nB = nA + 1;
        const float fA = feats[nA * D_ + c];
        const float fB = feats[nB * D_ + c];
        cfA[c] = fA;  cfB[c] = fB;
        const int* nnA = g_nn_idx + nA * K_;
        const int* nnB = g_nn_idx + nB * K_;
#pragma unroll
        for (int k = 0; k < K_; k++) {
            dA[k * C_ + c] = feats[(bbase + nnA[k]) * D_ + c] - fA;
            dB[k * C_ + c] = feats[(bbase + nnB[k]) * D_ + c] - fB;
        }
    }

#pragma unroll 1
    for (int i = 0; i < PAIRS_; i++) {
        const int nodeA = blockIdx.x * 16 + i * 4 + grp * 2;
        const int nodeB = nodeA + 1;
        __syncthreads();   // dbuf/cf for this pair ready; prev hbuf reads done

        // ---- prefetch next pair into registers (consumed after mid sync)
        float preA[K_], preB[K_];
        float fAn = 0.f, fBn = 0.f;
        if (i < PAIRS_ - 1) {
            const int mA = nodeA + 4, mB = nodeB + 4;
            const int* nnA = g_nn_idx + mA * K_;
            const int* nnB = g_nn_idx + mB * K_;
            fAn = feats[mA * D_ + c];
            fBn = feats[mB * D_ + c];
#pragma unroll
            for (int k = 0; k < K_; k++) {
                preA[k] = feats[(bbase + nnA[k]) * D_ + c];
                preB[k] = feats[(bbase + nnB[k]) * D_ + c];
            }
        }

        // ---- center contributions (both nodes)
        float ca0 = b1f, ca1 = 0.f, cb0 = b1f, cb1 = 0.f;
#pragma unroll
        for (int d = 0; d < D_; d += 2) {
            float2 va = *(const float2*)&cfA[d];
            float2 vb = *(const float2*)&cfB[d];
            ca0 += va.x * w1c_s[d * C_ + c];
            ca1 += va.y * w1c_s[(d + 1) * C_ + c];
            cb0 += vb.x * w1c_s[d * C_ + c];
            cb1 += vb.y * w1c_s[(d + 1) * C_ + c];
        }
        const unsigned long long pcA = pack2(ca0 + ca1, 0.f);
        const unsigned long long pcB = pack2(cb0 + cb1, 0.f);

        // ---- layer 1: both nodes, k-tiled 4 -> 8 independent chains
#pragma unroll 1
        for (int t = 0; t < K_; t += 4) {
            unsigned long long A0 = pcA, A1 = pcA, A2 = pcA, A3 = pcA;
            unsigned long long B0 = pcB, B1 = pcB, B2 = pcB, B3 = pcB;
            const float* ra = &dA[t * C_];
            const float* rb = &dB[t * C_];
#pragma unroll
            for (int d = 0; d < D_; d += 4) {
                const int w = d >> 1;
                ulonglong2 qa0 = *(const ulonglong2*)&ra[0 * C_ + d];
                ulonglong2 qa1 = *(const ulonglong2*)&ra[1 * C_ + d];
                ulonglong2 qa2 = *(const ulonglong2*)&ra[2 * C_ + d];
                ulonglong2 qa3 = *(const ulonglong2*)&ra[3 * C_ + d];
                ulonglong2 qb0 = *(const ulonglong2*)&rb[0 * C_ + d];
                ulonglong2 qb1 = *(const ulonglong2*)&rb[1 * C_ + d];
                ulonglong2 qb2 = *(const ulonglong2*)&rb[2 * C_ + d];
                ulonglong2 qb3 = *(const ulonglong2*)&rb[3 * C_ + d];
                A0 = ffma2(qa0.x, W1[w], A0);  A0 = ffma2(qa0.y, W1[w + 1], A0);
                A1 = ffma2(qa1.x, W1[w], A1);  A1 = ffma2(qa1.y, W1[w + 1], A1);
                A2 = ffma2(qa2.x, W1[w], A2);  A2 = ffma2(qa2.y, W1[w + 1], A2);
                A3 = ffma2(qa3.x, W1[w], A3);  A3 = ffma2(qa3.y, W1[w + 1], A3);
                B0 = ffma2(qb0.x, W1[w], B0);  B0 = ffma2(qb0.y, W1[w + 1], B0);
                B1 = ffma2(qb1.x, W1[w], B1);  B1 = ffma2(qb1.y, W1[w + 1], B1);
                B2 = ffma2(qb2.x, W1[w], B2);  B2 = ffma2(qb2.y, W1[w + 1], B2);
                B3 = ffma2(qb3.x, W1[w], B3);  B3 = ffma2(qb3.y, W1[w + 1], B3);
            }
            float2 a0 = unpack2(A0), a1 = unpack2(A1), a2 = unpack2(A2), a3 = unpack2(A3);
            float2 b0 = unpack2(B0), b1_ = unpack2(B1), b2_ = unpack2(B2), b3 = unpack2(B3);
            hA[(t + 0) * C_ + c] = fmaxf(a0.x + a0.y, 0.f);
            hA[(t + 1) * C_ + c] = fmaxf(a1.x + a1.y, 0.f);
            hA[(t + 2) * C_ + c] = fmaxf(a2.x + a2.y, 0.f);
            hA[(t + 3) * C_ + c] = fmaxf(a3.x + a3.y, 0.f);
            hB[(t + 0) * C_ + c] = fmaxf(b0.x + b0.y, 0.f);
            hB[(t + 1) * C_ + c] = fmaxf(b1_.x + b1_.y, 0.f);
            hB[(t + 2) * C_ + c] = fmaxf(b2_.x + b2_.y, 0.f);
            hB[(t + 3) * C_ + c] = fmaxf(b3.x + b3.y, 0.f);
        }
        __syncthreads();   // hbuf ready; dbuf dead (all layer-1 reads done)

        // ---- store prefetched gather into (now dead) dbuf/cf
        if (i < PAIRS_ - 1) {
            cfA[c] = fAn;  cfB[c] = fBn;
#pragma unroll
            for (int k = 0; k < K_; k++) {
                dA[k * C_ + c] = preA[k] - fAn;
                dB[k * C_ + c] = preB[k] - fBn;
            }
        }

        // ---- layer 2: both nodes, k-tiled 4; mean accumulate
        const unsigned long long pb = pack2(b2f, 0.f);
        float accA = 0.f, accB = 0.f;
#pragma unroll 1
        for (int t = 0; t < K_; t += 4) {
            unsigned long long A0 = pb, A1 = pb, A2 = pb, A3 = pb;
            unsigned long long B0 = pb, B1 = pb, B2 = pb, B3 = pb;
            const float* ra = &hA[t * C_];
            const float* rb = &hB[t * C_];
#pragma unroll
            for (int e = 0; e < C_; e += 4) {
                const int w = e >> 1;
                ulonglong2 qa0 = *(const ulonglong2*)&ra[0 * C_ + e];
                ulonglong2 qa1 = *(const ulonglong2*)&ra[1 * C_ + e];
                ulonglong2 qa2 = *(const ulonglong2*)&ra[2 * C_ + e];
                ulonglong2 qa3 = *(const ulonglong2*)&ra[3 * C_ + e];
                ulonglong2 qb0 = *(const ulonglong2*)&rb[0 * C_ + e];
                ulonglong2 qb1 = *(const ulonglong2*)&rb[1 * C_ + e];
                ulonglong2 qb2 = *(const ulonglong2*)&rb[2 * C_ + e];
                ulonglong2 qb3 = *(const ulonglong2*)&rb[3 * C_ + e];
                A0 = ffma2(qa0.x, W2[w], A0);  A0 = ffma2(qa0.y, W2[w + 1], A0);
                A1 = ffma2(qa1.x, W2[w], A1);  A1 = ffma2(qa1.y, W2[w + 1], A1);
                A2 = ffma2(qa2.x, W2[w], A2);  A2 = ffma2(qa2.y, W2[w + 1], A2);
                A3 = ffma2(qa3.x, W2[w], A3);  A3 = ffma2(qa3.y, W2[w + 1], A3);
                B0 = ffma2(qb0.x, W2[w], B0);  B0 = ffma2(qb0.y, W2[w + 1], B0);
                B1 = ffma2(qb1.x, W2[w], B1);  B1 = ffma2(qb1.y, W2[w + 1], B1);
                B2 = ffma2(qb2.x, W2[w], B2);  B2 = ffma2(qb2.y, W2[w + 1], B2);
                B3 = ffma2(qb3.x, W2[w], B3);  B3 = ffma2(qb3.y, W2[w + 1], B3);
            }
            float2 a0 = unpack2(A0), a1 = unpack2(A1), a2 = unpack2(A2), a3 = unpack2(A3);
            float2 b0 = unpack2(B0), b1_ = unpack2(B1), b2_ = unpack2(B2), b3 = unpack2(B3);
            accA += fmaxf(a0.x + a0.y, 0.f) + fmaxf(a1.x + a1.y, 0.f)
                  + fmaxf(a2.x + a2.y, 0.f) + fmaxf(a3.x + a3.y, 0.f);
            accB += fmaxf(b0.x + b0.y, 0.f) + fmaxf(b1_.x + b1_.y, 0.f)
                  + fmaxf(b2_.x + b2_.y, 0.f) + fmaxf(b3.x + b3.y, 0.f);
        }
        out[nodeA * C_ + c] = accA * (1.0f / K_);
        out[nodeB * C_ + c] = accB * (1.0f / K_);
    }
}

// ---------------------------------------------------------------------------
// MEASUREMENT ROUND: edgeconv_kernel is launched TWICE (idempotent — writes
// the same output). total(R8) - total(R5) isolates edgeconv's cost so R9 can
// attack the actual dominant phase.
// ---------------------------------------------------------------------------
extern "C" void kernel_launch(void* const* d_in, const int* in_sizes, int n_in,
                              void* d_out, int out_size)
{
    const float* feats = (const float*)d_in[0];
    const float* adj   = (const float*)d_in[1];
    const float* w1    = (const float*)d_in[2];
    const float* b1    = (const float*)d_in[3];
    const float* g1    = (const float*)d_in[4];
    const float* be1   = (const float*)d_in[5];
    const float* mu1   = (const float*)d_in[6];
    const float* v1    = (const float*)d_in[7];
    const float* w2    = (const float*)d_in[8];
    const float* b2    = (const float*)d_in[9];
    const float* g2    = (const float*)d_in[10];
    const float* be2   = (const float*)d_in[11];
    const float* mu2   = (const float*)d_in[12];
    const float* v2    = (const float*)d_in[13];
    float* out = (float*)d_out;

    static int smem_set = 0;
    if (!smem_set) {
        cudaFuncSetAttribute(edgeconv_kernel,
                             cudaFuncAttributeMaxDynamicSharedMemorySize,
                             SM_FLOATS * (int)sizeof(float));
        smem_set = 1;
    }

    extract_f0_kernel<<<(B_ * N_ + 1023) / 1024, 1024>>>(feats);
    topk_kernel<<<B_ * N_, 256>>>(adj);
    edgeconv_kernel<<<(B_ * N_) / 16, 128, SM_FLOATS * (int)sizeof(float)>>>(
        feats, w1, b1, g1, be1, mu1, v1, w2, b2, g2, be2, mu2, v2, out);
    edgeconv_kernel<<<(B_ * N_) / 16, 128, SM_FLOATS * (int)sizeof(float)>>>(
        feats, w1, b1, g1, be1, mu1, v1, w2, b2, g2, be2, mu2, v2, out);
}

// round 9
// speedup vs baseline: 1.3056x; 1.3056x over previous
#include <cuda_runtime.h>
#include <cstdint>

#define B_ 16
#define N_ 1024
#define D_ 64
#define C_ 64
#define K_ 20
#define EPS_ 0.001f
#define NTILES_ 4096          // 16384 nodes / 4 per tile
#define GRID2_ 296

// scratch (no cudaMalloc allowed)
__device__ int   g_nn_idx[B_ * N_ * K_];
__device__ float g_f0[B_ * N_];

// ---------------------------------------------------------------------------
// helpers
// ---------------------------------------------------------------------------
__device__ __forceinline__ uint32_t cvt_tf32(float x) {
    uint32_t r; asm("cvt.rna.tf32.f32 %0, %1;" : "=r"(r) : "f"(x)); return r;
}
__device__ __forceinline__ float tf32f(float x) {
    return __uint_as_float(cvt_tf32(x));
}
__device__ __forceinline__ void mma_tf32(float d[4],
                                         uint32_t a0, uint32_t a1, uint32_t a2, uint32_t a3,
                                         uint32_t b0, uint32_t b1) {
    asm("mma.sync.aligned.m16n8k8.row.col.f32.tf32.tf32.f32 "
        "{%0,%1,%2,%3}, {%4,%5,%6,%7}, {%8,%9}, {%0,%1,%2,%3};"
        : "+f"(d[0]), "+f"(d[1]), "+f"(d[2]), "+f"(d[3])
        : "r"(a0), "r"(a1), "r"(a2), "r"(a3), "r"(b0), "r"(b1));
}

// smem float offsets
// A: 128 blocks (s16 in [0,16), m in [0,8)) x 128 floats = 16384 floats (64KB)
// H: 64 blocks (s in [0,8), m in [0,8)) x 128 floats = 8192 floats (32KB)
#define SM_A 0
#define SM_H 16384
#define SMEM_F (16384 + 8192)

// ---------------------------------------------------------------------------
// Kernel 0: densify f0
// ---------------------------------------------------------------------------
__global__ void extract_f0_kernel(const float* __restrict__ feats) {
    int i = blockIdx.x * blockDim.x + threadIdx.x;
    if (i < B_ * N_) g_f0[i] = feats[(size_t)i * D_];
}

// ---------------------------------------------------------------------------
// Kernel 1: exact top-20 (proven)
// ---------------------------------------------------------------------------
__global__ void topk_kernel(const float* __restrict__ adj) {
    const int row  = blockIdx.x;
    const int b    = row >> 10;
    const int tid  = threadIdx.x;
    const int lane = tid & 31;
    const int wid  = tid >> 5;

    const float  f0n  = g_f0[row];
    const float* arow = adj + (size_t)row * N_;
    const float* f0b  = g_f0 + b * N_;

    unsigned long long key[4];
#pragma unroll
    for (int t = 0; t < 4; t++) {
        int j = tid + t * 256;
        float a = arow[j] * fabsf(f0b[j] - f0n);
        key[t] = ((unsigned long long)__float_as_uint(a) << 32) | (unsigned)j;
    }
#define CSWP(x, y) { unsigned long long lo = (x) < (y) ? (x) : (y); \
                     unsigned long long hi = (x) < (y) ? (y) : (x); (x) = lo; (y) = hi; }
    CSWP(key[0], key[1]); CSWP(key[2], key[3]);
    CSWP(key[0], key[2]); CSWP(key[1], key[3]);
    CSWP(key[1], key[2]);
#undef CSWP

    __shared__ unsigned long long cand[8][K_];

#pragma unroll 1
    for (int i = 0; i < K_; i++) {
        unsigned v = (unsigned)(key[0] >> 32);
        unsigned m = __reduce_min_sync(0xffffffffu, v);
        unsigned ic = (v == m) ? (unsigned)key[0] : 0xffffffffu;
        unsigned mi = __reduce_min_sync(0xffffffffu, ic);
        if (lane == 0) cand[wid][i] = ((unsigned long long)m << 32) | mi;
        if (v == m && (unsigned)key[0] == mi) {
            key[0] = key[1]; key[1] = key[2]; key[2] = key[3];
            key[3] = ~0ULL;
        }
    }
    __syncthreads();

    if (wid == 0) {
        int q = 0;
        const int out_base = row * K_;
#pragma unroll 1
        for (int i = 0; i < K_; i++) {
            unsigned long long myk = (lane < 8) ? cand[lane][q] : ~0ULL;
            unsigned v = (unsigned)(myk >> 32);
            unsigned m = __reduce_min_sync(0xffffffffu, v);
            unsigned ic = (v == m) ? (unsigned)myk : 0xffffffffu;
            unsigned mi = __reduce_min_sync(0xffffffffu, ic);
            if (lane == 0) g_nn_idx[out_base + i] = (int)mi;
            if (v == m && (unsigned)myk == mi) q++;
        }
    }
}

// ---------------------------------------------------------------------------
// Kernel 2: MMA edgeconv v2.
// Tile = 4 nodes x 32 padded k = 128 rows. GEMM1: K=128 (k<64: diff dims,
// k>=64: center dims -> center contribution folded into the GEMM). GEMM2: K=64.
// A/H stored in fragment-native 16B units [a0,a2,a1,a3] at unit pi(lane)=
// g + 8*t4 within 512B blocks (s*8+m) -> 1 LDS.128 per fragment, conflict-free.
// Single-pass tf32 both operands (R7 measured A-only rounding at 6.3e-5).
// Warp w owns cols [16w,16w+16); weights live in registers as B fragments.
// Mean over k<20 in registers (masked accumulate + xor-shfl).
// ---------------------------------------------------------------------------
__global__ void __launch_bounds__(128, 2) edgeconv_mma_kernel(
    const float* __restrict__ feats,
    const float* __restrict__ w1,  const float* __restrict__ b1,
    const float* __restrict__ g1,  const float* __restrict__ be1,
    const float* __restrict__ mu1, const float* __restrict__ v1,
    const float* __restrict__ w2,  const float* __restrict__ b2,
    const float* __restrict__ g2,  const float* __restrict__ be2,
    const float* __restrict__ mu2, const float* __restrict__ v2,
    float* __restrict__ out)
{
    extern __shared__ __align__(16) float sm[];

    const int tid  = threadIdx.x;
    const int wid  = tid >> 5;
    const int lane = tid & 31;
    const int g    = lane >> 2;     // fragment group row
    const int t4   = lane & 3;      // thread in group
    const uint32_t pi = (uint32_t)(g + 8 * t4);   // unit index within block

    // ---- B fragments in registers (folded BN scale), single tf32 ----
    uint32_t B1[2][16][2];   // [n-half t][k-block s16][j]; s16>=8 = center
    uint32_t B2[2][8][2];
#pragma unroll
    for (int t = 0; t < 2; t++) {
        const int nb = wid * 16 + t * 8 + g;
        const float s1n = g1[nb] * rsqrtf(v1[nb] + EPS_);
        const float s2n = g2[nb] * rsqrtf(v2[nb] + EPS_);
#pragma unroll
        for (int s = 0; s < 16; s++) {
#pragma unroll
            for (int j = 0; j < 2; j++) {
                const int kin = (s & 7) * 8 + t4 + j * 4;
                const int row1 = (s < 8) ? (D_ + kin) : kin;   // diff half / center half
                B1[t][s][j] = cvt_tf32(w1[row1 * C_ + nb] * s1n);
                if (s < 8)
                    B2[t][s][j] = cvt_tf32(w2[kin * C_ + nb] * s2n);
            }
        }
    }
    // folded biases for this thread's 4 output columns
    float bf1v[2][2], bf2v[2][2];
#pragma unroll
    for (int t = 0; t < 2; t++)
#pragma unroll
        for (int j = 0; j < 2; j++) {
            const int c = wid * 16 + t * 8 + t4 * 2 + j;
            const float s1c = g1[c] * rsqrtf(v1[c] + EPS_);
            const float s2c = g2[c] * rsqrtf(v2[c] + EPS_);
            bf1v[t][j] = (b1[c] - mu1[c]) * s1c + be1[c];
            bf2v[t][j] = (b2[c] - mu2[c]) * s2c + be2[c];
        }

#pragma unroll 1
    for (int tile = blockIdx.x; tile < NTILES_; tile += GRID2_) {
        const int tbase = tile * 4;
        const int bb    = (tbase >> 10) << 10;

        // ---- gather: thread = row r; writes diff (s<8) + center (s>=8) ----
        {
            const int r = tid, kk = r & 31, node = tbase + (r >> 5);
            const int m = r >> 4, grow = r & 7, rb = (r >> 3) & 1;
            const float4* ctr4 = (const float4*)(feats + (size_t)node * D_);
            const float4* src4 = ctr4;
            if (kk < K_) {
                const int nbr = g_nn_idx[node * K_ + kk];
                src4 = (const float4*)(feats + (size_t)(bb + nbr) * D_);
            }
#pragma unroll
            for (int s = 0; s < 8; s++) {
                float4 c0 = ctr4[2 * s], c1 = ctr4[2 * s + 1];
                float v[8];
                if (kk < K_) {
                    float4 x0 = src4[2 * s], x1 = src4[2 * s + 1];
                    v[0] = x0.x - c0.x; v[1] = x0.y - c0.y;
                    v[2] = x0.z - c0.z; v[3] = x0.w - c0.w;
                    v[4] = x1.x - c1.x; v[5] = x1.y - c1.y;
                    v[6] = x1.z - c1.z; v[7] = x1.w - c1.w;
                } else {
#pragma unroll
                    for (int q = 0; q < 8; q++) v[q] = 0.f;
                }
                float cv[8] = {c0.x, c0.y, c0.z, c0.w, c1.x, c1.y, c1.z, c1.w};
#pragma unroll
                for (int tw = 0; tw < 4; tw++) {
                    // diff block s
                    float2 p; p.x = tf32f(v[tw]); p.y = tf32f(v[tw + 4]);
                    *(float2*)(sm + SM_A + (s * 8 + m) * 128
                               + (grow + 8 * tw) * 4 + rb * 2) = p;
                    // center block s+8
                    float2 q; q.x = tf32f(cv[tw]); q.y = tf32f(cv[tw + 4]);
                    *(float2*)(sm + SM_A + ((s + 8) * 8 + m) * 128
                               + (grow + 8 * tw) * 4 + rb * 2) = q;
                }
            }
        }
        __syncthreads();

        // ---- layer 1: D = A @ W1 (K=128), epilogue -> H (fragment layout) ----
#pragma unroll 1
        for (int m = 0; m < 8; m++) {
            float d0[4] = {0.f, 0.f, 0.f, 0.f};
            float d1[4] = {0.f, 0.f, 0.f, 0.f};
#pragma unroll
            for (int s = 0; s < 16; s++) {
                float4 q = *(const float4*)(sm + SM_A + (s * 8 + m) * 128 + pi * 4);
                uint32_t a0 = __float_as_uint(q.x), a2 = __float_as_uint(q.y);
                uint32_t a1 = __float_as_uint(q.z), a3 = __float_as_uint(q.w);
                mma_tf32(d0, a0, a1, a2, a3, B1[0][s][0], B1[0][s][1]);
                mma_tf32(d1, a0, a1, a2, a3, B1[1][s][0], B1[1][s][1]);
            }
            // epilogue: h = relu(d + b1f) -> H fragment units
#pragma unroll
            for (int t = 0; t < 2; t++) {
                const float* dd = t ? d1 : d0;
#pragma unroll
                for (int vq = 0; vq < 4; vq++) {
                    const int rb = vq >> 1, j = vq & 1;
                    const int e  = wid * 16 + t * 8 + t4 * 2 + j;
                    const int sp = e >> 3, t4p = e & 3, hi = (e >> 2) & 1;
                    sm[SM_H + (sp * 8 + m) * 128 + (g + 8 * t4p) * 4 + rb * 2 + hi]
                        = tf32f(fmaxf(dd[vq] + bf1v[t][j], 0.f));
                }
            }
        }
        __syncthreads();

        // ---- layer 2: D = H @ W2 (K=64); masked mean in registers ----
        float ysum[4][2][2];
#pragma unroll
        for (int ln = 0; ln < 4; ln++)
#pragma unroll
            for (int t = 0; t < 2; t++) { ysum[ln][t][0] = 0.f; ysum[ln][t][1] = 0.f; }

#pragma unroll 1
        for (int m = 0; m < 8; m++) {
            float d0[4] = {0.f, 0.f, 0.f, 0.f};
            float d1[4] = {0.f, 0.f, 0.f, 0.f};
#pragma unroll
            for (int s = 0; s < 8; s++) {
                float4 q = *(const float4*)(sm + SM_H + (s * 8 + m) * 128 + pi * 4);
                uint32_t a0 = __float_as_uint(q.x), a2 = __float_as_uint(q.y);
                uint32_t a1 = __float_as_uint(q.z), a3 = __float_as_uint(q.w);
                mma_tf32(d0, a0, a1, a2, a3, B2[0][s][0], B2[0][s][1]);
                mma_tf32(d1, a0, a1, a2, a3, B2[1][s][0], B2[1][s][1]);
            }
            const int node = m >> 1;
            if ((m & 1) == 0) {
                // rows 8rb+g are all < 16 < 20: both rb valid
                ysum[node][0][0] += fmaxf(d0[0] + bf2v[0][0], 0.f) + fmaxf(d0[2] + bf2v[0][0], 0.f);
                ysum[node][0][1] += fmaxf(d0[1] + bf2v[0][1], 0.f) + fmaxf(d0[3] + bf2v[0][1], 0.f);
                ysum[node][1][0] += fmaxf(d1[0] + bf2v[1][0], 0.f) + fmaxf(d1[2] + bf2v[1][0], 0.f);
                ysum[node][1][1] += fmaxf(d1[1] + bf2v[1][1], 0.f) + fmaxf(d1[3] + bf2v[1][1], 0.f);
            } else if (g < 4) {
                // rows 16+8rb+g valid iff rb==0 and g<4
                ysum[node][0][0] += fmaxf(d0[0] + bf2v[0][0], 0.f);
                ysum[node][0][1] += fmaxf(d0[1] + bf2v[0][1], 0.f);
                ysum[node][1][0] += fmaxf(d1[0] + bf2v[1][0], 0.f);
                ysum[node][1][1] += fmaxf(d1[1] + bf2v[1][1], 0.f);
            }
        }

        // reduce over g lanes and store
#pragma unroll
        for (int ln = 0; ln < 4; ln++)
#pragma unroll
            for (int t = 0; t < 2; t++)
#pragma unroll
                for (int j = 0; j < 2; j++) {
                    float v = ysum[ln][t][j];
                    v += __shfl_xor_sync(0xffffffffu, v, 4);
                    v += __shfl_xor_sync(0xffffffffu, v, 8);
                    v += __shfl_xor_sync(0xffffffffu, v, 16);
                    if (lane < 4)
                        out[(size_t)(tbase + ln) * C_ + wid * 16 + t * 8 + t4 * 2 + j]
                            = v * (1.0f / K_);
                }
        __syncthreads();   // H fully consumed before next tile's epilogue writes
    }
}

// ---------------------------------------------------------------------------
extern "C" void kernel_launch(void* const* d_in, const int* in_sizes, int n_in,
                              void* d_out, int out_size)
{
    const float* feats = (const float*)d_in[0];
    const float* adj   = (const float*)d_in[1];
    const float* w1    = (const float*)d_in[2];
    const float* b1    = (const float*)d_in[3];
    const float* g1    = (const float*)d_in[4];
    const float* be1   = (const float*)d_in[5];
    const float* mu1   = (const float*)d_in[6];
    const float* v1    = (const float*)d_in[7];
    const float* w2    = (const float*)d_in[8];
    const float* b2    = (const float*)d_in[9];
    const float* g2    = (const float*)d_in[10];
    const float* be2   = (const float*)d_in[11];
    const float* mu2   = (const float*)d_in[12];
    const float* v2    = (const float*)d_in[13];
    float* out = (float*)d_out;

    static int init_done = 0;
    if (!init_done) {
        cudaFuncSetAttribute(edgeconv_mma_kernel,
                             cudaFuncAttributeMaxDynamicSharedMemorySize,
                             SMEM_F * (int)sizeof(float));
        init_done = 1;
    }

    extract_f0_kernel<<<(B_ * N_ + 1023) / 1024, 1024>>>(feats);
    topk_kernel<<<B_ * N_, 256>>>(adj);
    edgeconv_mma_kernel<<<GRID2_, 128, SMEM_F * (int)sizeof(float)>>>(
        feats, w1, b1, g1, be1, mu1, v1, w2, b2, g2, be2, mu2, v2, out);
}

// round 10
// speedup vs baseline: 1.7093x; 1.3092x over previous
#include <cuda_runtime.h>

#define B_ 16
#define N_ 1024
#define D_ 64
#define C_ 64
#define K_ 20
#define EPS_ 0.001f
#define ROWP_ 68     // padded activation row (floats): d<32 at [0..31], d>=32 at [36..67]
#define HOFF_ 36

// scratch (no cudaMalloc allowed)
__device__ int   g_nn_idx[B_ * N_ * K_];
__device__ float g_f0[B_ * N_];
__device__ float g_cpart[B_ * N_ * C_];   // 4 MB: center-part + bias1, exact fp32

// ---------------------------------------------------------------------------
// packed fp32x2 helpers (sm_103a FFMA2)
// ---------------------------------------------------------------------------
__device__ __forceinline__ unsigned long long pack2(float x, float y) {
    float2 f = make_float2(x, y);
    return *reinterpret_cast<unsigned long long*>(&f);
}
__device__ __forceinline__ float2 unpack2(unsigned long long u) {
    return *reinterpret_cast<float2*>(&u);
}
__device__ __forceinline__ unsigned long long ffma2(unsigned long long a,
                                                    unsigned long long b,
                                                    unsigned long long c) {
    unsigned long long d;
    asm("fma.rn.f32x2 %0, %1, %2, %3;" : "=l"(d) : "l"(a), "l"(b), "l"(c));
    return d;
}

// ---------------------------------------------------------------------------
// Kernel 0: densify f0 = feats[:,:,0]
// ---------------------------------------------------------------------------
__global__ void extract_f0_kernel(const float* __restrict__ feats) {
    int i = blockIdx.x * blockDim.x + threadIdx.x;
    if (i < B_ * N_) g_f0[i] = feats[(size_t)i * D_];
}

// ---------------------------------------------------------------------------
// Kernel 1: exact top-20 (proven; REDUX argmin, lowest-index tie-break)
// ---------------------------------------------------------------------------
__global__ void topk_kernel(const float* __restrict__ adj) {
    const int row  = blockIdx.x;
    const int b    = row >> 10;
    const int tid  = threadIdx.x;
    const int lane = tid & 31;
    const int wid  = tid >> 5;

    const float  f0n  = g_f0[row];
    const float* arow = adj + (size_t)row * N_;
    const float* f0b  = g_f0 + b * N_;

    unsigned long long key[4];
#pragma unroll
    for (int t = 0; t < 4; t++) {
        int j = tid + t * 256;
        float a = arow[j] * fabsf(f0b[j] - f0n);
        key[t] = ((unsigned long long)__float_as_uint(a) << 32) | (unsigned)j;
    }
#define CSWP(x, y) { unsigned long long lo = (x) < (y) ? (x) : (y); \
                     unsigned long long hi = (x) < (y) ? (y) : (x); (x) = lo; (y) = hi; }
    CSWP(key[0], key[1]); CSWP(key[2], key[3]);
    CSWP(key[0], key[2]); CSWP(key[1], key[3]);
    CSWP(key[1], key[2]);
#undef CSWP

    __shared__ unsigned long long cand[8][K_];

#pragma unroll 1
    for (int i = 0; i < K_; i++) {
        unsigned v = (unsigned)(key[0] >> 32);
        unsigned m = __reduce_min_sync(0xffffffffu, v);
        unsigned ic = (v == m) ? (unsigned)key[0] : 0xffffffffu;
        unsigned mi = __reduce_min_sync(0xffffffffu, ic);
        if (lane == 0) cand[wid][i] = ((unsigned long long)m << 32) | mi;
        if (v == m && (unsigned)key[0] == mi) {
            key[0] = key[1]; key[1] = key[2]; key[2] = key[3];
            key[3] = ~0ULL;
        }
    }
    __syncthreads();

    if (wid == 0) {
        int q = 0;
        const int out_base = row * K_;
#pragma unroll 1
        for (int i = 0; i < K_; i++) {
            unsigned long long myk = (lane < 8) ? cand[lane][q] : ~0ULL;
            unsigned v = (unsigned)(myk >> 32);
            unsigned m = __reduce_min_sync(0xffffffffu, v);
            unsigned ic = (v == m) ? (unsigned)myk : 0xffffffffu;
            unsigned mi = __reduce_min_sync(0xffffffffu, ic);
            if (lane == 0) g_nn_idx[out_base + i] = (int)mi;
            if (v == m && (unsigned)myk == mi) q++;
        }
    }
}

// ---------------------------------------------------------------------------
// Kernel 1.5: cpart[node][c] = b1f[c] + sum_d feats[node][d] * w1fold[d][c]
// Exact fp32; tiny (134 MFLOP). Transposed folded weights in smem (pad 65,
// scalar LDS, conflict-free: bank = (c + d) & 31, distinct across lanes).
// ---------------------------------------------------------------------------
__global__ void cpart_kernel(const float* __restrict__ feats,
                             const float* __restrict__ w1, const float* __restrict__ b1,
                             const float* __restrict__ g1, const float* __restrict__ be1,
                             const float* __restrict__ mu1, const float* __restrict__ v1)
{
    __shared__ float w1ct[C_ * 65];
    const int tid = threadIdx.x;        // 256
    const int c   = tid & 63;
    const int sub = tid >> 6;           // 4 subgroups x 8 nodes

    for (int idx = tid; idx < D_ * C_; idx += 256) {
        const int cc = idx & 63, d = idx >> 6;
        w1ct[cc * 65 + d] = w1[d * C_ + cc] * (g1[cc] * rsqrtf(v1[cc] + EPS_));
    }
    const float s1c = g1[c] * rsqrtf(v1[c] + EPS_);
    const float b1f = (b1[c] - mu1[c]) * s1c + be1[c];
    __syncthreads();

#pragma unroll 1
    for (int n = 0; n < 8; n++) {
        const int node = blockIdx.x * 32 + sub * 8 + n;
        const float* f = feats + (size_t)node * D_;
        const float* w = w1ct + c * 65;
        float s0 = 0.f, s1 = 0.f, s2 = 0.f, s3 = 0.f;
#pragma unroll
        for (int d = 0; d < D_; d += 4) {
            s0 += f[d + 0] * w[d + 0];
            s1 += f[d + 1] * w[d + 1];
            s2 += f[d + 2] * w[d + 2];
            s3 += f[d + 3] * w[d + 3];
        }
        g_cpart[node * C_ + c] = (s0 + s1) + (s2 + s3) + b1f;
    }
}

// ---------------------------------------------------------------------------
// Kernel 2: edgeconv, 2 channels/thread x half-reduction.
// lane = cp + 16*half; thread owns channels c0=wig*32+2cp, c1=c0+1 and
// reduction range d in [32*half, 32*half+32). Per k: 8 LDS.128 -> 32 FFMA2
// (1:4) + 2 SHFL.BFLY(16). Activation rows padded (68 floats, half1 at +36):
// all LDS/STS conflict-free. Center part read from g_cpart (precomputed).
// Block = 128 thr = 2 groups x 2 warps; 16 nodes/block, 8 serial per group.
// ---------------------------------------------------------------------------
__global__ void __launch_bounds__(128, 2) edgeconv_kernel(
    const float* __restrict__ feats,
    const float* __restrict__ w1,
    const float* __restrict__ w2,  const float* __restrict__ b2,
    const float* __restrict__ g2,  const float* __restrict__ be2,
    const float* __restrict__ mu2, const float* __restrict__ v2,
    const float* __restrict__ g1,  const float* __restrict__ v1,
    float* __restrict__ out)
{
    __shared__ __align__(16) float dbuf[2][2][K_ * ROWP_];
    __shared__ __align__(16) float hbuf[2][K_ * ROWP_];

    const int tid  = threadIdx.x;
    const int grp  = tid >> 6;
    const int gt   = tid & 63;
    const int wig  = gt >> 5;
    const int lane = tid & 31;
    const int cp   = lane & 15;
    const int half = lane >> 4;
    const int c0   = wig * 32 + cp * 2;
    const int c1   = c0 + 1;
    const int dbase = half * 32;
    const int bbase = ((blockIdx.x * 16) >> 10) << 10;   // b*N

    // folded weights for this thread's 2 channels, this half's 32 dims
    const float s1_0 = g1[c0] * rsqrtf(v1[c0] + EPS_);
    const float s1_1 = g1[c1] * rsqrtf(v1[c1] + EPS_);
    const float s2_0 = g2[c0] * rsqrtf(v2[c0] + EPS_);
    const float s2_1 = g2[c1] * rsqrtf(v2[c1] + EPS_);
    const float bf2_0 = (b2[c0] - mu2[c0]) * s2_0 + be2[c0];
    const float bf2_1 = (b2[c1] - mu2[c1]) * s2_1 + be2[c1];

    unsigned long long W1[2][16], W2[2][16];
#pragma unroll
    for (int i = 0; i < 16; i++) {
        const int d = dbase + 2 * i;
        W1[0][i] = pack2(w1[(D_ + d) * C_ + c0] * s1_0, w1[(D_ + d + 1) * C_ + c0] * s1_0);
        W1[1][i] = pack2(w1[(D_ + d) * C_ + c1] * s1_1, w1[(D_ + d + 1) * C_ + c1] * s1_1);
        W2[0][i] = pack2(w2[d * C_ + c0] * s2_0, w2[(d + 1) * C_ + c0] * s2_0);
        W2[1][i] = pack2(w2[d * C_ + c1] * s2_1, w2[(d + 1) * C_ + c1] * s2_1);
    }

    // gather mapping: thread = column cg for its group
    const int cg = gt;
    const int pg = cg + ((cg >= 32) ? 4 : 0);
    const int hw0 = c0 + ((c0 >= 32) ? 4 : 0);   // padded pos of c0
    const int hw1 = c1 + ((c1 >= 32) ? 4 : 0);

    // gather node i=0
    {
        const int node0 = blockIdx.x * 16 + grp * 8;
        const float fc = feats[node0 * D_ + cg];
        const int* nn = g_nn_idx + node0 * K_;
#pragma unroll
        for (int k = 0; k < K_; k++)
            dbuf[grp][0][k * ROWP_ + pg] = feats[(bbase + nn[k]) * D_ + cg] - fc;
    }

#pragma unroll 1
    for (int i = 0; i < 8; i++) {
        const int cur = i & 1, nxt = cur ^ 1;
        const int node = blockIdx.x * 16 + grp * 8 + i;
        __syncthreads();   // dbuf[cur] ready; prev hbuf reads done

        // prefetch node i+1
        float pre[K_];
        float fcn = 0.f;
        if (i < 7) {
            const int node2 = node + 1;
            const int* nn2 = g_nn_idx + node2 * K_;
            fcn = feats[node2 * D_ + cg];
#pragma unroll
            for (int k = 0; k < K_; k++)
                pre[k] = feats[(bbase + nn2[k]) * D_ + cg];
        }

        const float cpv0 = g_cpart[node * C_ + c0];
        const float cpv1 = g_cpart[node * C_ + c1];

        // ---- layer 1: all K, half-range, 2 channels
        const float* db = dbuf[grp][cur];
#pragma unroll 1
        for (int t = 0; t < K_; t += 4) {
            unsigned long long a00 = 0, a01 = 0, a10 = 0, a11 = 0;
            unsigned long long a20 = 0, a21 = 0, a30 = 0, a31 = 0;
            const float* r0 = db + (t + 0) * ROWP_ + half * HOFF_;
            const float* r1 = db + (t + 1) * ROWP_ + half * HOFF_;
            const float* r2 = db + (t + 2) * ROWP_ + half * HOFF_;
            const float* r3 = db + (t + 3) * ROWP_ + half * HOFF_;
#pragma unroll
            for (int d = 0; d < 32; d += 4) {
                const int w = d >> 1;
                ulonglong2 q0 = *(const ulonglong2*)&r0[d];
                ulonglong2 q1 = *(const ulonglong2*)&r1[d];
                ulonglong2 q2 = *(const ulonglong2*)&r2[d];
                ulonglong2 q3 = *(const ulonglong2*)&r3[d];
                a00 = ffma2(q0.x, W1[0][w], a00);  a00 = ffma2(q0.y, W1[0][w + 1], a00);
                a01 = ffma2(q0.x, W1[1][w], a01);  a01 = ffma2(q0.y, W1[1][w + 1], a01);
                a10 = ffma2(q1.x, W1[0][w], a10);  a10 = ffma2(q1.y, W1[0][w + 1], a10);
                a11 = ffma2(q1.x, W1[1][w], a11);  a11 = ffma2(q1.y, W1[1][w + 1], a11);
                a20 = ffma2(q2.x, W1[0][w], a20);  a20 = ffma2(q2.y, W1[0][w + 1], a20);
                a21 = ffma2(q2.x, W1[1][w], a21);  a21 = ffma2(q2.y, W1[1][w + 1], a21);
                a30 = ffma2(q3.x, W1[0][w], a30);  a30 = ffma2(q3.y, W1[0][w + 1], a30);
                a31 = ffma2(q3.x, W1[1][w], a31);  a31 = ffma2(q3.y, W1[1][w + 1], a31);
            }
#pragma unroll
            for (int k4 = 0; k4 < 4; k4++) {
                unsigned long long A0 = (k4 == 0) ? a00 : (k4 == 1) ? a10 : (k4 == 2) ? a20 : a30;
                unsigned long long A1 = (k4 == 0) ? a01 : (k4 == 1) ? a11 : (k4 == 2) ? a21 : a31;
                float2 u0 = unpack2(A0), u1 = unpack2(A1);
                float s0 = u0.x + u0.y, s1 = u1.x + u1.y;
                s0 += __shfl_xor_sync(0xffffffffu, s0, 16);
                s1 += __shfl_xor_sync(0xffffffffu, s1, 16);
                const float h = (half == 0) ? fmaxf(s0 + cpv0, 0.f)
                                            : fmaxf(s1 + cpv1, 0.f);
                hbuf[grp][(t + k4) * ROWP_ + (half == 0 ? hw0 : hw1)] = h;
            }
        }

        // store prefetched gather into dbuf[nxt]
        if (i < 7) {
#pragma unroll
            for (int k = 0; k < K_; k++)
                dbuf[grp][nxt][k * ROWP_ + pg] = pre[k] - fcn;
        }
        __syncthreads();   // hbuf ready

        // ---- layer 2: all K, half-range, 2 channels; mean accumulate
        const float* hb = hbuf[grp];
        float acc = 0.f;
#pragma unroll 1
        for (int t = 0; t < K_; t += 4) {
            unsigned long long a00 = 0, a01 = 0, a10 = 0, a11 = 0;
            unsigned long long a20 = 0, a21 = 0, a30 = 0, a31 = 0;
            const float* r0 = hb + (t + 0) * ROWP_ + half * HOFF_;
            const float* r1 = hb + (t + 1) * ROWP_ + half * HOFF_;
            const float* r2 = hb + (t + 2) * ROWP_ + half * HOFF_;
            const float* r3 = hb + (t + 3) * ROWP_ + half * HOFF_;
#pragma unroll
            for (int e = 0; e < 32; e += 4) {
                const int w = e >> 1;
                ulonglong2 q0 = *(const ulonglong2*)&r0[e];
                ulonglong2 q1 = *(const ulonglong2*)&r1[e];
                ulonglong2 q2 = *(const ulonglong2*)&r2[e];
                ulonglong2 q3 = *(const ulonglong2*)&r3[e];
                a00 = ffma2(q0.x, W2[0][w], a00);  a00 = ffma2(q0.y, W2[0][w + 1], a00);
                a01 = ffma2(q0.x, W2[1][w], a01);  a01 = ffma2(q0.y, W2[1][w + 1], a01);
                a10 = ffma2(q1.x, W2[0][w], a10);  a10 = ffma2(q1.y, W2[0][w + 1], a10);
                a11 = ffma2(q1.x, W2[1][w], a11);  a11 = ffma2(q1.y, W2[1][w + 1], a11);
                a20 = ffma2(q2.x, W2[0][w], a20);  a20 = ffma2(q2.y, W2[0][w + 1], a20);
                a21 = ffma2(q2.x, W2[1][w], a21);  a21 = ffma2(q2.y, W2[1][w + 1], a21);
                a30 = ffma2(q3.x, W2[0][w], a30);  a30 = ffma2(q3.y, W2[0][w + 1], a30);
                a31 = ffma2(q3.x, W2[1][w], a31);  a31 = ffma2(q3.y, W2[1][w + 1], a31);
            }
#pragma unroll
            for (int k4 = 0; k4 < 4; k4++) {
                unsigned long long A0 = (k4 == 0) ? a00 : (k4 == 1) ? a10 : (k4 == 2) ? a20 : a30;
                unsigned long long A1 = (k4 == 0) ? a01 : (k4 == 1) ? a11 : (k4 == 2) ? a21 : a31;
                float2 u0 = unpack2(A0), u1 = unpack2(A1);
                float s0 = u0.x + u0.y, s1 = u1.x + u1.y;
                s0 += __shfl_xor_sync(0xffffffffu, s0, 16);
                s1 += __shfl_xor_sync(0xffffffffu, s1, 16);
                acc += (half == 0) ? fmaxf(s0 + bf2_0, 0.f)
                                   : fmaxf(s1 + bf2_1, 0.f);
            }
        }
        out[node * C_ + (half == 0 ? c0 : c1)] = acc * (1.0f / K_);
    }
}

// ---------------------------------------------------------------------------
extern "C" void kernel_launch(void* const* d_in, const int* in_sizes, int n_in,
                              void* d_out, int out_size)
{
    const float* feats = (const float*)d_in[0];
    const float* adj   = (const float*)d_in[1];
    const float* w1    = (const float*)d_in[2];
    const float* b1    = (const float*)d_in[3];
    const float* g1    = (const float*)d_in[4];
    const float* be1   = (const float*)d_in[5];
    const float* mu1   = (const float*)d_in[6];
    const float* v1    = (const float*)d_in[7];
    const float* w2    = (const float*)d_in[8];
    const float* b2    = (const float*)d_in[9];
    const float* g2    = (const float*)d_in[10];
    const float* be2   = (const float*)d_in[11];
    const float* mu2   = (const float*)d_in[12];
    const float* v2    = (const float*)d_in[13];
    float* out = (float*)d_out;

    extract_f0_kernel<<<(B_ * N_ + 1023) / 1024, 1024>>>(feats);
    topk_kernel<<<B_ * N_, 256>>>(adj);
    cpart_kernel<<<(B_ * N_) / 32, 256>>>(feats, w1, b1, g1, be1, mu1, v1);
    edgeconv_kernel<<<(B_ * N_) / 16, 128>>>(feats, w1, w2, b2, g2, be2, mu2, v2,
                                             g1, v1, out);
}

// round 11
// speedup vs baseline: 2.1132x; 1.2363x over previous
#include <cuda_runtime.h>
#include <cstdint>

#define B_ 16
#define N_ 1024
#define D_ 64
#define C_ 64
#define K_ 20
#define EPS_ 0.001f
#define ROWP_ 68     // padded activation row (floats): d<32 at [0..31], d>=32 at [36..67]
#define HOFF_ 36
#define CANDCAP_ 1024

// scratch (no cudaMalloc allowed)
__device__ int   g_nn_idx[B_ * N_ * K_];
__device__ float g_f0[B_ * N_];
__device__ float g_cpart[B_ * N_ * C_];   // 4 MB: center-part + bias1, exact fp32

// ---------------------------------------------------------------------------
// packed fp32x2 helpers (sm_103a FFMA2)
// ---------------------------------------------------------------------------
__device__ __forceinline__ unsigned long long pack2(float x, float y) {
    float2 f = make_float2(x, y);
    return *reinterpret_cast<unsigned long long*>(&f);
}
__device__ __forceinline__ float2 unpack2(unsigned long long u) {
    return *reinterpret_cast<float2*>(&u);
}
__device__ __forceinline__ unsigned long long ffma2(unsigned long long a,
                                                    unsigned long long b,
                                                    unsigned long long c) {
    unsigned long long d;
    asm("fma.rn.f32x2 %0, %1, %2, %3;" : "=l"(d) : "l"(a), "l"(b), "l"(c));
    return d;
}

// ---------------------------------------------------------------------------
// Kernel 0: densify f0 = feats[:,:,0]
// ---------------------------------------------------------------------------
__global__ void extract_f0_kernel(const float* __restrict__ feats) {
    int i = blockIdx.x * blockDim.x + threadIdx.x;
    if (i < B_ * N_) g_f0[i] = feats[(size_t)i * D_];
}

// ---------------------------------------------------------------------------
// Kernel 1: top-20 smallest of a[j] = adj[b,n,j]*|f0[b,j]-f0[b,n]| per row,
// via 1024-bin histogram radix-select on float bits [31:22].
// Output is the exact SET of the 20 smallest (value,index) keys (unique keys;
// downstream mean over k is order-invariant, so order is free).
// ---------------------------------------------------------------------------
__global__ void topk_kernel(const float* __restrict__ adj) {
    __shared__ uint32_t hist[1024];
    __shared__ uint32_t scan_s[256];
    __shared__ unsigned long long cand[CANDCAP_];
    __shared__ int ctr[4];     // [0]=ncand, [1]=below-pos, [2]=T, [3]=cnt_below

    const int row = blockIdx.x;            // b*N + n
    const int b   = row >> 10;
    const int tid = threadIdx.x;           // 256 threads

    for (int i = tid; i < 1024; i += 256) hist[i] = 0;
    if (tid < 4) ctr[tid] = 0;
    __syncthreads();

    const float  f0n  = g_f0[row];
    const float* arow = adj + (size_t)row * N_;
    const float* f0b  = g_f0 + b * N_;

    uint32_t vb[4];
#pragma unroll
    for (int t = 0; t < 4; t++) {
        const int j = tid + t * 256;
        float a = arow[j] * fabsf(f0b[j] - f0n);
        vb[t] = __float_as_uint(a);        // a >= 0: u32 order == float order
        atomicAdd(&hist[vb[t] >> 22], 1u);
    }
    __syncthreads();

    // partial sums: thread i covers bins [4i, 4i+4)
    {
        uint32_t s = hist[4 * tid] + hist[4 * tid + 1]
                   + hist[4 * tid + 2] + hist[4 * tid + 3];
        scan_s[tid] = s;
    }
    __syncthreads();

    // warp 0: find threshold bin T (cumulative count reaches K) + cnt_below
    if (tid < 32) {
        uint32_t w = 0;
#pragma unroll
        for (int q = 0; q < 8; q++) w += scan_s[tid * 8 + q];
        uint32_t inc = w;
#pragma unroll
        for (int off = 1; off < 32; off <<= 1) {
            uint32_t o = __shfl_up_sync(0xffffffffu, inc, off);
            if (tid >= off) inc += o;
        }
        const uint32_t excl = inc - w;
        const bool hit = (excl < K_) && (inc >= K_);
        const uint32_t mask = __ballot_sync(0xffffffffu, hit);
        const int seg = __ffs(mask) - 1;
        if (tid == seg) {
            uint32_t cum = excl;
            int T = 0; uint32_t below = 0;
            for (int q = 0; q < 8; q++) {
                const uint32_t c = scan_s[seg * 8 + q];
                if (cum + c >= K_) {
                    const int bb2 = (seg * 8 + q) * 4;
                    for (int z = 0; z < 4; z++) {
                        const uint32_t hc = hist[bb2 + z];
                        if (cum + hc >= K_) { T = bb2 + z; below = cum; break; }
                        cum += hc;
                    }
                    break;
                }
                cum += c;
            }
            ctr[2] = T;
            ctr[3] = (int)below;
        }
    }
    __syncthreads();
    const uint32_t T = (uint32_t)ctr[2];
    const int cnt_below = ctr[3];

    // collect: below-T indices straight out; bin==T keys to candidate list
    int* outp = g_nn_idx + row * K_;
#pragma unroll
    for (int t = 0; t < 4; t++) {
        const uint32_t bin = vb[t] >> 22;
        const int j = tid + t * 256;
        if (bin < T) {
            const int p = atomicAdd(&ctr[1], 1);
            outp[p] = j;
        } else if (bin == T) {
            const int p = atomicAdd(&ctr[0], 1);
            cand[p] = ((unsigned long long)vb[t] << 32) | (unsigned)j;
        }
    }
    __syncthreads();

    // rank-count select of r = K - cnt_below smallest among candidates
    const int ncand = ctr[0];
    const int r = K_ - cnt_below;
    for (int i = tid; i < ncand; i += 256) {
        const unsigned long long me = cand[i];
        int rank = 0;
        for (int q = 0; q < ncand; q++) rank += (cand[q] < me);
        if (rank < r) outp[cnt_below + rank] = (int)(unsigned)(me & 0xffffffffu);
    }
}

// ---------------------------------------------------------------------------
// Kernel 1.5: cpart[node][c] = b1f[c] + sum_d feats[node][d] * w1fold[d][c]
// ---------------------------------------------------------------------------
__global__ void cpart_kernel(const float* __restrict__ feats,
                             const float* __restrict__ w1, const float* __restrict__ b1,
                             const float* __restrict__ g1, const float* __restrict__ be1,
                             const float* __restrict__ mu1, const float* __restrict__ v1)
{
    __shared__ float w1ct[C_ * 65];
    const int tid = threadIdx.x;        // 256
    const int c   = tid & 63;
    const int sub = tid >> 6;           // 4 subgroups x 8 nodes

    for (int idx = tid; idx < D_ * C_; idx += 256) {
        const int cc = idx & 63, d = idx >> 6;
        w1ct[cc * 65 + d] = w1[d * C_ + cc] * (g1[cc] * rsqrtf(v1[cc] + EPS_));
    }
    const float s1c = g1[c] * rsqrtf(v1[c] + EPS_);
    const float b1f = (b1[c] - mu1[c]) * s1c + be1[c];
    __syncthreads();

#pragma unroll 1
    for (int n = 0; n < 8; n++) {
        const int node = blockIdx.x * 32 + sub * 8 + n;
        const float* f = feats + (size_t)node * D_;
        const float* w = w1ct + c * 65;
        float s0 = 0.f, s1 = 0.f, s2 = 0.f, s3 = 0.f;
#pragma unroll
        for (int d = 0; d < D_; d += 4) {
            s0 += f[d + 0] * w[d + 0];
            s1 += f[d + 1] * w[d + 1];
            s2 += f[d + 2] * w[d + 2];
            s3 += f[d + 3] * w[d + 3];
        }
        g_cpart[node * C_ + c] = (s0 + s1) + (s2 + s3) + b1f;
    }
}

// ---------------------------------------------------------------------------
// Kernel 2: edgeconv (R10 structure, proven 146us): 2 channels/thread x
// half-reduction, padded smem rows, prefetch pipeline, cpart precomputed.
// ---------------------------------------------------------------------------
__global__ void __launch_bounds__(128, 2) edgeconv_kernel(
    const float* __restrict__ feats,
    const float* __restrict__ w1,
    const float* __restrict__ w2,  const float* __restrict__ b2,
    const float* __restrict__ g2,  const float* __restrict__ be2,
    const float* __restrict__ mu2, const float* __restrict__ v2,
    const float* __restrict__ g1,  const float* __restrict__ v1,
    float* __restrict__ out)
{
    __shared__ __align__(16) float dbuf[2][2][K_ * ROWP_];
    __shared__ __align__(16) float hbuf[2][K_ * ROWP_];

    const int tid  = threadIdx.x;
    const int grp  = tid >> 6;
    const int gt   = tid & 63;
    const int wig  = gt >> 5;
    const int lane = tid & 31;
    const int cp   = lane & 15;
    const int half = lane >> 4;
    const int c0   = wig * 32 + cp * 2;
    const int c1   = c0 + 1;
    const int dbase = half * 32;
    const int bbase = ((blockIdx.x * 16) >> 10) << 10;   // b*N

    const float s1_0 = g1[c0] * rsqrtf(v1[c0] + EPS_);
    const float s1_1 = g1[c1] * rsqrtf(v1[c1] + EPS_);
    const float s2_0 = g2[c0] * rsqrtf(v2[c0] + EPS_);
    const float s2_1 = g2[c1] * rsqrtf(v2[c1] + EPS_);
    const float bf2_0 = (b2[c0] - mu2[c0]) * s2_0 + be2[c0];
    const float bf2_1 = (b2[c1] - mu2[c1]) * s2_1 + be2[c1];

    unsigned long long W1[2][16], W2[2][16];
#pragma unroll
    for (int i = 0; i < 16; i++) {
        const int d = dbase + 2 * i;
        W1[0][i] = pack2(w1[(D_ + d) * C_ + c0] * s1_0, w1[(D_ + d + 1) * C_ + c0] * s1_0);
        W1[1][i] = pack2(w1[(D_ + d) * C_ + c1] * s1_1, w1[(D_ + d + 1) * C_ + c1] * s1_1);
        W2[0][i] = pack2(w2[d * C_ + c0] * s2_0, w2[(d + 1) * C_ + c0] * s2_0);
        W2[1][i] = pack2(w2[d * C_ + c1] * s2_1, w2[(d + 1) * C_ + c1] * s2_1);
    }

    const int cg = gt;
    const int pg = cg + ((cg >= 32) ? 4 : 0);
    const int hw0 = c0 + ((c0 >= 32) ? 4 : 0);
    const int hw1 = c1 + ((c1 >= 32) ? 4 : 0);

    // gather node i=0
    {
        const int node0 = blockIdx.x * 16 + grp * 8;
        const float fc = feats[node0 * D_ + cg];
        const int* nn = g_nn_idx + node0 * K_;
#pragma unroll
        for (int k = 0; k < K_; k++)
            dbuf[grp][0][k * ROWP_ + pg] = feats[(bbase + nn[k]) * D_ + cg] - fc;
    }

#pragma unroll 1
    for (int i = 0; i < 8; i++) {
        const int cur = i & 1, nxt = cur ^ 1;
        const int node = blockIdx.x * 16 + grp * 8 + i;
        __syncthreads();

        float pre[K_];
        float fcn = 0.f;
        if (i < 7) {
            const int node2 = node + 1;
            const int* nn2 = g_nn_idx + node2 * K_;
            fcn = feats[node2 * D_ + cg];
#pragma unroll
            for (int k = 0; k < K_; k++)
                pre[k] = feats[(bbase + nn2[k]) * D_ + cg];
        }

        const float cpv0 = g_cpart[node * C_ + c0];
        const float cpv1 = g_cpart[node * C_ + c1];

        const float* db = dbuf[grp][cur];
#pragma unroll 1
        for (int t = 0; t < K_; t += 4) {
            unsigned long long a00 = 0, a01 = 0, a10 = 0, a11 = 0;
            unsigned long long a20 = 0, a21 = 0, a30 = 0, a31 = 0;
            const float* r0 = db + (t + 0) * ROWP_ + half * HOFF_;
            const float* r1 = db + (t + 1) * ROWP_ + half * HOFF_;
            const float* r2 = db + (t + 2) * ROWP_ + half * HOFF_;
            const float* r3 = db + (t + 3) * ROWP_ + half * HOFF_;
#pragma unroll
            for (int d = 0; d < 32; d += 4) {
                const int w = d >> 1;
                ulonglong2 q0 = *(const ulonglong2*)&r0[d];
                ulonglong2 q1 = *(const ulonglong2*)&r1[d];
                ulonglong2 q2 = *(const ulonglong2*)&r2[d];
                ulonglong2 q3 = *(const ulonglong2*)&r3[d];
                a00 = ffma2(q0.x, W1[0][w], a00);  a00 = ffma2(q0.y, W1[0][w + 1], a00);
                a01 = ffma2(q0.x, W1[1][w], a01);  a01 = ffma2(q0.y, W1[1][w + 1], a01);
                a10 = ffma2(q1.x, W1[0][w], a10);  a10 = ffma2(q1.y, W1[0][w + 1], a10);
                a11 = ffma2(q1.x, W1[1][w], a11);  a11 = ffma2(q1.y, W1[1][w + 1], a11);
                a20 = ffma2(q2.x, W1[0][w], a20);  a20 = ffma2(q2.y, W1[0][w + 1], a20);
                a21 = ffma2(q2.x, W1[1][w], a21);  a21 = ffma2(q2.y, W1[1][w + 1], a21);
                a30 = ffma2(q3.x, W1[0][w], a30);  a30 = ffma2(q3.y, W1[0][w + 1], a30);
                a31 = ffma2(q3.x, W1[1][w], a31);  a31 = ffma2(q3.y, W1[1][w + 1], a31);
            }
#pragma unroll
            for (int k4 = 0; k4 < 4; k4++) {
                unsigned long long A0 = (k4 == 0) ? a00 : (k4 == 1) ? a10 : (k4 == 2) ? a20 : a30;
                unsigned long long A1 = (k4 == 0) ? a01 : (k4 == 1) ? a11 : (k4 == 2) ? a21 : a31;
                float2 u0 = unpack2(A0), u1 = unpack2(A1);
                float s0 = u0.x + u0.y, s1 = u1.x + u1.y;
                s0 += __shfl_xor_sync(0xffffffffu, s0, 16);
                s1 += __shfl_xor_sync(0xffffffffu, s1, 16);
                const float h = (half == 0) ? fmaxf(s0 + cpv0, 0.f)
                                            : fmaxf(s1 + cpv1, 0.f);
                hbuf[grp][(t + k4) * ROWP_ + (half == 0 ? hw0 : hw1)] = h;
            }
        }

        if (i < 7) {
#pragma unroll
            for (int k = 0; k < K_; k++)
                dbuf[grp][nxt][k * ROWP_ + pg] = pre[k] - fcn;
        }
        __syncthreads();

        const float* hb = hbuf[grp];
        float acc = 0.f;
#pragma unroll 1
        for (int t = 0; t < K_; t += 4) {
            unsigned long long a00 = 0, a01 = 0, a10 = 0, a11 = 0;
            unsigned long long a20 = 0, a21 = 0, a30 = 0, a31 = 0;
            const float* r0 = hb + (t + 0) * ROWP_ + half * HOFF_;
            const float* r1 = hb + (t + 1) * ROWP_ + half * HOFF_;
            const float* r2 = hb + (t + 2) * ROWP_ + half * HOFF_;
            const float* r3 = hb + (t + 3) * ROWP_ + half * HOFF_;
#pragma unroll
            for (int e = 0; e < 32; e += 4) {
                const int w = e >> 1;
                ulonglong2 q0 = *(const ulonglong2*)&r0[e];
                ulonglong2 q1 = *(const ulonglong2*)&r1[e];
                ulonglong2 q2 = *(const ulonglong2*)&r2[e];
                ulonglong2 q3 = *(const ulonglong2*)&r3[e];
                a00 = ffma2(q0.x, W2[0][w], a00);  a00 = ffma2(q0.y, W2[0][w + 1], a00);
                a01 = ffma2(q0.x, W2[1][w], a01);  a01 = ffma2(q0.y, W2[1][w + 1], a01);
                a10 = ffma2(q1.x, W2[0][w], a10);  a10 = ffma2(q1.y, W2[0][w + 1], a10);
                a11 = ffma2(q1.x, W2[1][w], a11);  a11 = ffma2(q1.y, W2[1][w + 1], a11);
                a20 = ffma2(q2.x, W2[0][w], a20);  a20 = ffma2(q2.y, W2[0][w + 1], a20);
                a21 = ffma2(q2.x, W2[1][w], a21);  a21 = ffma2(q2.y, W2[1][w + 1], a21);
                a30 = ffma2(q3.x, W2[0][w], a30);  a30 = ffma2(q3.y, W2[0][w + 1], a30);
                a31 = ffma2(q3.x, W2[1][w], a31);  a31 = ffma2(q3.y, W2[1][w + 1], a31);
            }
#pragma unroll
            for (int k4 = 0; k4 < 4; k4++) {
                unsigned long long A0 = (k4 == 0) ? a00 : (k4 == 1) ? a10 : (k4 == 2) ? a20 : a30;
                unsigned long long A1 = (k4 == 0) ? a01 : (k4 == 1) ? a11 : (k4 == 2) ? a21 : a31;
                float2 u0 = unpack2(A0), u1 = unpack2(A1);
                float s0 = u0.x + u0.y, s1 = u1.x + u1.y;
                s0 += __shfl_xor_sync(0xffffffffu, s0, 16);
                s1 += __shfl_xor_sync(0xffffffffu, s1, 16);
                acc += (half == 0) ? fmaxf(s0 + bf2_0, 0.f)
                                   : fmaxf(s1 + bf2_1, 0.f);
            }
        }
        out[node * C_ + (half == 0 ? c0 : c1)] = acc * (1.0f / K_);
    }
}

// ---------------------------------------------------------------------------
extern "C" void kernel_launch(void* const* d_in, const int* in_sizes, int n_in,
                              void* d_out, int out_size)
{
    const float* feats = (const float*)d_in[0];
    const float* adj   = (const float*)d_in[1];
    const float* w1    = (const float*)d_in[2];
    const float* b1    = (const float*)d_in[3];
    const float* g1    = (const float*)d_in[4];
    const float* be1   = (const float*)d_in[5];
    const float* mu1   = (const float*)d_in[6];
    const float* v1    = (const float*)d_in[7];
    const float* w2    = (const float*)d_in[8];
    const float* b2    = (const float*)d_in[9];
    const float* g2    = (const float*)d_in[10];
    const float* be2   = (const float*)d_in[11];
    const float* mu2   = (const float*)d_in[12];
    const float* v2    = (const float*)d_in[13];
    float* out = (float*)d_out;

    extract_f0_kernel<<<(B_ * N_ + 1023) / 1024, 1024>>>(feats);
    topk_kernel<<<B_ * N_, 256>>>(adj);
    cpart_kernel<<<(B_ * N_) / 32, 256>>>(feats, w1, b1, g1, be1, mu1, v1);
    edgeconv_kernel<<<(B_ * N_) / 16, 128>>>(feats, w1, w2, b2, g2, be2, mu2, v2,
                                             g1, v1, out);
}